// round 10
// baseline (speedup 1.0000x reference)
#include <cuda_runtime.h>

// Net_multi_11390253269716: 3-level GCN U-Net, 784x480 grid, C=32.
// R10: fully fused GCN kernels: aggregate raw X (transforms on the fly)
//      then staged-shared gemm in the same block. No Y buffer at all.
//      R3-proven 6-launch CSR build. 12 launches total.

#define NXg 784
#define NYg 480
#define C 32
#define N0 (NXg * NYg)        // 376320
#define N1 (N0 / 4)           // 94080
#define N2 (N0 / 16)          // 23520
#define E0 (4 * N0)
#define E1 (4 * N1)
#define E2 (4 * N2)
#define ETOT (E0 + E1 + E2)   // 1975680
#define M (N0 + N1 + N2)      // 493920
#define GB1 N0
#define GB2 (N0 + N1)
#define SCAN_NBLK ((M + 1023) / 1024)   // 483
#define NPB 128               // nodes per fused-GCN block

typedef unsigned long long ull;

// ---------------- scratch ----------------
__device__ float4 g_X1[N0 * 8];   // relu(fc1(x))
__device__ float4 g_H [N0 * 8];   // GCN1 out (pre-relu)
__device__ float4 g_G2[N1 * 8];
__device__ float4 g_G4[N1 * 8];
__device__ float4 g_G3[N2 * 8];
__device__ int   g_cnt[M];
__device__ int   g_rowptr[M + 1];
__device__ int   g_eix[ETOT];
__device__ float g_dinv[M];
__device__ int   g_bsum[SCAN_NBLK];

// ---------------- helpers ----------------
__device__ __forceinline__ ull pk2(float a, float b) {
    ull r; asm("mov.b64 %0, {%1, %2};" : "=l"(r) : "f"(a), "f"(b)); return r;
}
__device__ __forceinline__ ull fma2_(ull a, ull b, ull c) {
    ull d; asm("fma.rn.f32x2 %0, %1, %2, %3;" : "=l"(d) : "l"(a), "l"(b), "l"(c)); return d;
}
__device__ __forceinline__ ull add2_(ull a, ull b) {
    ull d; asm("add.rn.f32x2 %0, %1, %2;" : "=l"(d) : "l"(a), "l"(b)); return d;
}
__device__ __forceinline__ float2 up2_(ull v) {
    float2 f; asm("mov.b64 {%0, %1}, %2;" : "=f"(f.x), "=f"(f.y) : "l"(v)); return f;
}
__device__ __forceinline__ float4 relu4(float4 v) {
    v.x = fmaxf(v.x, 0.f); v.y = fmaxf(v.y, 0.f);
    v.z = fmaxf(v.z, 0.f); v.w = fmaxf(v.w, 0.f);
    return v;
}

// ---------------- CSR build (R3-proven) ----------------
__global__ void zero_cnt() {
    int i = blockIdx.x * blockDim.x + threadIdx.x;
    if (i < M) g_cnt[i] = 0;
}

__global__ void hist3(const int* __restrict__ d0, const int* __restrict__ d1,
                      const int* __restrict__ d2) {
    int t = blockIdx.x * blockDim.x + threadIdx.x;
    int g;
    if (t < E0) g = d0[t];
    else if (t < E0 + E1) g = GB1 + d1[t - E0];
    else if (t < ETOT) g = GB2 + d2[t - E0 - E1];
    else return;
    atomicAdd(&g_cnt[g], 1);
}

__global__ void scanA() {
    __shared__ int sb[256];
    int tid = threadIdx.x;
    int base = blockIdx.x * 1024 + tid * 4;
    int v = 0;
    #pragma unroll
    for (int k = 0; k < 4; k++) if (base + k < M) v += g_cnt[base + k];
    sb[tid] = v; __syncthreads();
    for (int off = 128; off; off >>= 1) {
        if (tid < off) sb[tid] += sb[tid + off];
        __syncthreads();
    }
    if (tid == 0) g_bsum[blockIdx.x] = sb[0];
}

__global__ void scanB() {
    __shared__ int sb[512];
    int tid = threadIdx.x;
    int v = (tid < SCAN_NBLK) ? g_bsum[tid] : 0;
    sb[tid] = v; __syncthreads();
    for (int off = 1; off < 512; off <<= 1) {
        int t = (tid >= off) ? sb[tid - off] : 0;
        __syncthreads();
        sb[tid] += t;
        __syncthreads();
    }
    if (tid < SCAN_NBLK) g_bsum[tid] = sb[tid] - v;
}

__global__ void scanC() {
    __shared__ int sb[256];
    int tid = threadIdx.x;
    int base = blockIdx.x * 1024 + tid * 4;
    int v[4], p[4], tsum = 0;
    #pragma unroll
    for (int k = 0; k < 4; k++) {
        v[k] = (base + k < M) ? g_cnt[base + k] : 0;
        p[k] = tsum; tsum += v[k];
    }
    sb[tid] = tsum; __syncthreads();
    for (int off = 1; off < 256; off <<= 1) {
        int t = (tid >= off) ? sb[tid - off] : 0;
        __syncthreads();
        sb[tid] += t;
        __syncthreads();
    }
    int off0 = g_bsum[blockIdx.x] + sb[tid] - tsum;
    #pragma unroll
    for (int k = 0; k < 4; k++) {
        int i = base + k;
        if (i < M) {
            g_rowptr[i] = off0 + p[k];
            g_dinv[i] = rsqrtf((float)v[k] + 1.0f);
            g_cnt[i] = 0;
        }
    }
    if (blockIdx.x == 0 && tid == 0) g_rowptr[M] = ETOT;
}

__global__ void fill3(const int* __restrict__ ei0, const int* __restrict__ ei1,
                      const int* __restrict__ ei2) {
    int t = blockIdx.x * blockDim.x + threadIdx.x;
    int g, s;
    if (t < E0)           { g = ei0[E0 + t];                 s = ei0[t]; }
    else if (t < E0 + E1) { int e = t - E0;      g = GB1 + ei1[E1 + e]; s = ei1[e]; }
    else if (t < ETOT)    { int e = t - E0 - E1; g = GB2 + ei2[E2 + e]; s = ei2[e]; }
    else return;
    int pos = g_rowptr[g] + atomicAdd(&g_cnt[g], 1);
    g_eix[pos] = s;
}

// ---------------- fc1: X1 = relu(x @ fc1_w + fc1_b), 8 thr/node -------------
__global__ void fc1_kernel(const float4* __restrict__ x,
                           const float* __restrict__ fc1w,
                           const float* __restrict__ fc1b,
                           float4* __restrict__ X1, int n)
{
    __shared__ float4 sfw[32];
    __shared__ float4 sfb[8];
    int tid = threadIdx.x;
    if (tid < 32) sfw[tid] = ((const float4*)fc1w)[tid];
    if (tid < 8)  sfb[tid] = ((const float4*)fc1b)[tid];
    __syncthreads();
    int t = blockIdx.x * blockDim.x + tid;
    int node = t >> 3, sub = t & 7;
    if (node >= n) return;
    float4 xin = __ldg(&x[node]);
    float4 h = sfb[sub];
    float4 r0 = sfw[sub], r1 = sfw[8 + sub], r2 = sfw[16 + sub], r3 = sfw[24 + sub];
    h.x += xin.x * r0.x + xin.y * r1.x + xin.z * r2.x + xin.w * r3.x;
    h.y += xin.x * r0.y + xin.y * r1.y + xin.z * r2.y + xin.w * r3.y;
    h.z += xin.x * r0.z + xin.y * r1.z + xin.z * r2.z + xin.w * r3.z;
    h.w += xin.x * r0.w + xin.y * r1.w + xin.z * r2.w + xin.w * r3.w;
    X1[node * 8 + sub] = relu4(h);
}

// ---------------- fused GCN: phase A (aggregate) + phase B (gemm) -----------
// Phase A: 2 threads per node, 16 channels each. XLOAD(sidx) must set v0..v3
// (the 4 channel-quads [half, half+4) of source row sidx).
#define GCN_PREAMBLE(wptr, bptr)                                          \
    __shared__ ulonglong2 swu[256];                                       \
    __shared__ float4 sx[NPB * 9];                                        \
    __shared__ float4 sbb[8];                                             \
    int tid = threadIdx.x;                                                \
    swu[tid] = ((const ulonglong2*)(wptr))[tid];                          \
    if (tid < 8) sbb[tid] = ((const float4*)(bptr))[tid];

#define GCN_PHASE_A(n_, gb_, XLOAD)                                       \
    int ln = tid >> 1;                                                    \
    int node = blockIdx.x * NPB + ln;                                     \
    int half = (tid & 1) * 4;                                             \
    if (node < n_) {                                                      \
        int gn = (gb_) + node;                                            \
        int beg = g_rowptr[gn], end = g_rowptr[gn + 1];                   \
        float dd = g_dinv[gn];                                            \
        float4 a0 = {0,0,0,0}, a1 = a0, a2 = a0, a3 = a0;                 \
        float4 v0, v1, v2, v3;                                            \
        for (int p = beg; p < end; p++) {                                 \
            int s = g_eix[p];                                             \
            float nm = g_dinv[(gb_) + s];                                 \
            XLOAD(s);                                                     \
            a0.x += v0.x*nm; a0.y += v0.y*nm; a0.z += v0.z*nm; a0.w += v0.w*nm; \
            a1.x += v1.x*nm; a1.y += v1.y*nm; a1.z += v1.z*nm; a1.w += v1.w*nm; \
            a2.x += v2.x*nm; a2.y += v2.y*nm; a2.z += v2.z*nm; a2.w += v2.w*nm; \
            a3.x += v3.x*nm; a3.y += v3.y*nm; a3.z += v3.z*nm; a3.w += v3.w*nm; \
        }                                                                 \
        XLOAD(node);                                                      \
        a0.x = dd*(a0.x + dd*v0.x); a0.y = dd*(a0.y + dd*v0.y);           \
        a0.z = dd*(a0.z + dd*v0.z); a0.w = dd*(a0.w + dd*v0.w);           \
        a1.x = dd*(a1.x + dd*v1.x); a1.y = dd*(a1.y + dd*v1.y);           \
        a1.z = dd*(a1.z + dd*v1.z); a1.w = dd*(a1.w + dd*v1.w);           \
        a2.x = dd*(a2.x + dd*v2.x); a2.y = dd*(a2.y + dd*v2.y);           \
        a2.z = dd*(a2.z + dd*v2.z); a2.w = dd*(a2.w + dd*v2.w);           \
        a3.x = dd*(a3.x + dd*v3.x); a3.y = dd*(a3.y + dd*v3.y);           \
        a3.z = dd*(a3.z + dd*v3.z); a3.w = dd*(a3.w + dd*v3.w);           \
        sx[ln * 9 + half + 0] = a0;                                       \
        sx[ln * 9 + half + 1] = a1;                                       \
        sx[ln * 9 + half + 2] = a2;                                       \
        sx[ln * 9 + half + 3] = a3;                                       \
    }

// Phase B: R9 staged gemm + bias. Group lanes [grp*8, grp*8+8) share nodes.
#define GCN_PHASE_B(n_, OUT_)                                             \
    __syncthreads();                                                      \
    int lane = tid & 31;                                                  \
    int sub = lane & 7, grp = lane >> 3;                                  \
    int lbase = (tid >> 5) * 16 + grp;                                    \
    ull a01[4] = {0, 0, 0, 0}, a23[4] = {0, 0, 0, 0};                     \
    _Pragma("unroll")                                                     \
    for (int g = 0; g < 8; g++) {                                         \
        ulonglong2 w0 = swu[(4 * g + 0) * 8 + sub];                       \
        ulonglong2 w1 = swu[(4 * g + 1) * 8 + sub];                       \
        ulonglong2 w2 = swu[(4 * g + 2) * 8 + sub];                       \
        ulonglong2 w3 = swu[(4 * g + 3) * 8 + sub];                       \
        _Pragma("unroll")                                                 \
        for (int j = 0; j < 4; j++) {                                     \
            float4 xv = sx[(lbase + 4 * j) * 9 + g];                      \
            a01[j] = fma2_(pk2(xv.x, xv.x), w0.x, a01[j]);                \
            a23[j] = fma2_(pk2(xv.x, xv.x), w0.y, a23[j]);                \
            a01[j] = fma2_(pk2(xv.y, xv.y), w1.x, a01[j]);                \
            a23[j] = fma2_(pk2(xv.y, xv.y), w1.y, a23[j]);                \
            a01[j] = fma2_(pk2(xv.z, xv.z), w2.x, a01[j]);                \
            a23[j] = fma2_(pk2(xv.z, xv.z), w2.y, a23[j]);                \
            a01[j] = fma2_(pk2(xv.w, xv.w), w3.x, a01[j]);                \
            a23[j] = fma2_(pk2(xv.w, xv.w), w3.y, a23[j]);                \
        }                                                                 \
    }                                                                     \
    ull bb01 = pk2(sbb[sub].x, sbb[sub].y);                               \
    ull bb23 = pk2(sbb[sub].z, sbb[sub].w);                               \
    _Pragma("unroll")                                                     \
    for (int j = 0; j < 4; j++) {                                         \
        int nd = blockIdx.x * NPB + lbase + 4 * j;                        \
        if (nd < n_) {                                                    \
            ulonglong2 r;                                                 \
            r.x = add2_(a01[j], bb01);                                    \
            r.y = add2_(a23[j], bb23);                                    \
            ((ulonglong2*)(OUT_))[nd * 8 + sub] = r;                      \
        }                                                                 \
    }

// --- GCN1: X = X1[s] (already relu'd) ---
#define XL1(sidx) do { const float4* xs = X1 + (sidx) * 8 + half;         \
    v0 = xs[0]; v1 = xs[1]; v2 = xs[2]; v3 = xs[3]; } while (0)
__global__ void __launch_bounds__(256)
gcn1(const float4* __restrict__ X1, const float* __restrict__ w,
     const float* __restrict__ b, float4* __restrict__ OUT, int n)
{
    GCN_PREAMBLE(w, b)
    GCN_PHASE_A(n, 0, XL1)
    GCN_PHASE_B(n, OUT)
}

// --- GCN2/3: X = relu(SRC[downmap(s)]) ---
#define XLD(sidx) do {                                                    \
    int ix = (sidx) / hy, iy = (sidx) - ix * hy;                          \
    const float4* xs = SRC + ((2 * ix) * (2 * hy) + 2 * iy) * 8 + half;   \
    v0 = relu4(xs[0]); v1 = relu4(xs[1]);                                 \
    v2 = relu4(xs[2]); v3 = relu4(xs[3]); } while (0)
__global__ void __launch_bounds__(256)
gcn_down(const float4* __restrict__ SRC, const float* __restrict__ w,
         const float* __restrict__ b, float4* __restrict__ OUT,
         int n, int gb, int hy)
{
    GCN_PREAMBLE(w, b)
    GCN_PHASE_A(n, gb, XLD)
    GCN_PHASE_B(n, OUT)
}

// --- GCN4/5: X = relu(BASE[s]) + relu(CRS[parent(s)]) ---
#define XLU(sidx) do {                                                    \
    int ix = (sidx) / hy, iy = (sidx) - ix * hy;                          \
    int cn = (ix >> 1) * (hy >> 1) + (iy >> 1);                           \
    const float4* xb = BASE + (sidx) * 8 + half;                          \
    const float4* xc = CRS + cn * 8 + half;                               \
    float4 b0 = relu4(xb[0]), b1 = relu4(xb[1]);                          \
    float4 b2 = relu4(xb[2]), b3 = relu4(xb[3]);                          \
    float4 c0 = relu4(xc[0]), c1 = relu4(xc[1]);                          \
    float4 c2 = relu4(xc[2]), c3 = relu4(xc[3]);                          \
    v0 = make_float4(b0.x+c0.x, b0.y+c0.y, b0.z+c0.z, b0.w+c0.w);         \
    v1 = make_float4(b1.x+c1.x, b1.y+c1.y, b1.z+c1.z, b1.w+c1.w);         \
    v2 = make_float4(b2.x+c2.x, b2.y+c2.y, b2.z+c2.z, b2.w+c2.w);         \
    v3 = make_float4(b3.x+c3.x, b3.y+c3.y, b3.z+c3.z, b3.w+c3.w); } while (0)
__global__ void __launch_bounds__(256)
gcn_up(const float4* __restrict__ BASE, const float4* __restrict__ CRS,
       const float* __restrict__ w, const float* __restrict__ b,
       float4* __restrict__ OUT, int n, int gb, int hy)
{
    GCN_PREAMBLE(w, b)
    GCN_PHASE_A(n, gb, XLU)
    GCN_PHASE_B(n, OUT)
}

// --- GCN5 + fc2 epilogue ---
__global__ void __launch_bounds__(256)
gcn_up_fc2(const float4* __restrict__ BASE, const float4* __restrict__ CRS,
           const float* __restrict__ w, const float* __restrict__ b,
           const float* __restrict__ w2, const float* __restrict__ b2,
           float* __restrict__ out, int n, int gb, int hy)
{
    GCN_PREAMBLE(w, b)
    __shared__ float sw2[96];
    if (tid < 96) sw2[tid] = w2[tid];
    GCN_PHASE_A(n, gb, XLU)
    __syncthreads();
    int lane = tid & 31;
    int sub = lane & 7, grp = lane >> 3;
    int lbase = (tid >> 5) * 16 + grp;
    ull a01[4] = {0, 0, 0, 0}, a23[4] = {0, 0, 0, 0};
    #pragma unroll
    for (int g = 0; g < 8; g++) {
        ulonglong2 w0 = swu[(4 * g + 0) * 8 + sub];
        ulonglong2 w1 = swu[(4 * g + 1) * 8 + sub];
        ulonglong2 w2v = swu[(4 * g + 2) * 8 + sub];
        ulonglong2 w3 = swu[(4 * g + 3) * 8 + sub];
        #pragma unroll
        for (int j = 0; j < 4; j++) {
            float4 xv = sx[(lbase + 4 * j) * 9 + g];
            a01[j] = fma2_(pk2(xv.x, xv.x), w0.x, a01[j]);
            a23[j] = fma2_(pk2(xv.x, xv.x), w0.y, a23[j]);
            a01[j] = fma2_(pk2(xv.y, xv.y), w1.x, a01[j]);
            a23[j] = fma2_(pk2(xv.y, xv.y), w1.y, a23[j]);
            a01[j] = fma2_(pk2(xv.z, xv.z), w2v.x, a01[j]);
            a23[j] = fma2_(pk2(xv.z, xv.z), w2v.y, a23[j]);
            a01[j] = fma2_(pk2(xv.w, xv.w), w3.x, a01[j]);
            a23[j] = fma2_(pk2(xv.w, xv.w), w3.y, a23[j]);
        }
    }
    ull bb01 = pk2(sbb[sub].x, sbb[sub].y);
    ull bb23 = pk2(sbb[sub].z, sbb[sub].w);
    int c = 4 * sub;
    #pragma unroll
    for (int j = 0; j < 4; j++) {
        int nd = blockIdx.x * NPB + lbase + 4 * j;
        if (nd >= n) continue;
        float2 v01 = up2_(add2_(a01[j], bb01));
        float2 v23 = up2_(add2_(a23[j], bb23));
        float4 v = relu4(make_float4(v01.x, v01.y, v23.x, v23.y));
        float p0 = v.x*sw2[(c+0)*3+0] + v.y*sw2[(c+1)*3+0] + v.z*sw2[(c+2)*3+0] + v.w*sw2[(c+3)*3+0];
        float p1 = v.x*sw2[(c+0)*3+1] + v.y*sw2[(c+1)*3+1] + v.z*sw2[(c+2)*3+1] + v.w*sw2[(c+3)*3+1];
        float p2 = v.x*sw2[(c+0)*3+2] + v.y*sw2[(c+1)*3+2] + v.z*sw2[(c+2)*3+2] + v.w*sw2[(c+3)*3+2];
        #pragma unroll
        for (int off = 4; off; off >>= 1) {
            p0 += __shfl_down_sync(0xffffffffu, p0, off, 8);
            p1 += __shfl_down_sync(0xffffffffu, p1, off, 8);
            p2 += __shfl_down_sync(0xffffffffu, p2, off, 8);
        }
        if (sub == 0) {
            out[nd * 3 + 0] = p0 + __ldg(&b2[0]);
            out[nd * 3 + 1] = p1 + __ldg(&b2[1]);
            out[nd * 3 + 2] = p2 + __ldg(&b2[2]);
        }
    }
}

// ---------------------------------------------------------------------------
static inline int ceil_div(int a, int b) { return (a + b - 1) / b; }

extern "C" void kernel_launch(void* const* d_in, const int* in_sizes, int n_in,
                              void* d_out, int out_size) {
    const float* x     = (const float*)d_in[0];
    const float* fc1_w = (const float*)d_in[1];
    const float* fc1_b = (const float*)d_in[2];
    const float* w1 = (const float*)d_in[3];  const float* b1 = (const float*)d_in[4];
    const float* w2 = (const float*)d_in[5];  const float* b2 = (const float*)d_in[6];
    const float* w3 = (const float*)d_in[7];  const float* b3 = (const float*)d_in[8];
    const float* w4 = (const float*)d_in[9];  const float* b4 = (const float*)d_in[10];
    const float* w5 = (const float*)d_in[11]; const float* b5 = (const float*)d_in[12];
    const float* fc2_w = (const float*)d_in[13];
    const float* fc2_b = (const float*)d_in[14];
    const int* ei0 = (const int*)d_in[18];
    const int* ei1 = (const int*)d_in[19];
    const int* ei2 = (const int*)d_in[20];
    float* out = (float*)d_out;

    float4 *X1, *H, *G2, *G4, *G3;
    cudaGetSymbolAddress((void**)&X1, g_X1);
    cudaGetSymbolAddress((void**)&H,  g_H);
    cudaGetSymbolAddress((void**)&G2, g_G2);
    cudaGetSymbolAddress((void**)&G4, g_G4);
    cudaGetSymbolAddress((void**)&G3, g_G3);

    const int TB = 256;

    // 0-2: CSR build start
    zero_cnt<<<ceil_div(M, TB), TB>>>();
    hist3<<<ceil_div(ETOT, TB), TB>>>(ei0 + E0, ei1 + E1, ei2 + E2);
    scanA<<<SCAN_NBLK, 256>>>();
    // 3: fc1 (CSR-independent; profiled launch)
    fc1_kernel<<<ceil_div(N0 * 8, TB), TB>>>((const float4*)x, fc1_w, fc1_b, X1, N0);
    // 4-6: CSR build rest
    scanB<<<1, 512>>>();
    scanC<<<SCAN_NBLK, 256>>>();
    fill3<<<ceil_div(ETOT, TB), TB>>>(ei0, ei1, ei2);

    // 7: GCN1  H = agg(X1)@w1 + b1
    gcn1<<<ceil_div(N0, NPB), TB>>>(X1, w1, b1, H, N0);
    // 8: GCN2  G2 = agg(down(relu(H)))@w2 + b2
    gcn_down<<<ceil_div(N1, NPB), TB>>>(H, w2, b2, G2, N1, GB1, NYg / 2);
    // 9: GCN3  G3 = agg(down(relu(G2)))@w3 + b3
    gcn_down<<<ceil_div(N2, NPB), TB>>>(G2, w3, b3, G3, N2, GB2, NYg / 4);
    // 10: GCN4 G4 = agg(relu(G2)+up(relu(G3)))@w4 + b4
    gcn_up<<<ceil_div(N1, NPB), TB>>>(G2, G3, w4, b4, G4, N1, GB1, NYg / 2);
    // 11: GCN5 + fc2 -> out
    gcn_up_fc2<<<ceil_div(N0, NPB), TB>>>(H, G4, w5, b5, fc2_w, fc2_b, out,
                                          N0, 0, NYg);

    (void)in_sizes; (void)n_in; (void)out_size;
}

// round 11
// speedup vs baseline: 1.0798x; 1.0798x over previous
#include <cuda_runtime.h>

// Net_multi_11390253269716: 3-level GCN U-Net, 784x480 grid, C=32.
// R11: R9 base (238us) + dual-node interleaved gathers (2x MLP/thread),
//      4-launch CSR build (fused scan, count-down fill, no zero pass).

#define NXg 784
#define NYg 480
#define C 32
#define N0 (NXg * NYg)        // 376320
#define N1 (N0 / 4)           // 94080
#define N2 (N0 / 16)          // 23520
#define E0 (4 * N0)
#define E1 (4 * N1)
#define E2 (4 * N2)
#define ETOT (E0 + E1 + E2)   // 1975680
#define M (N0 + N1 + N2)      // 493920
#define GB1 N0
#define GB2 (N0 + N1)
#define SCAN_NBLK ((M + 1023) / 1024)   // 483
#define NPB 128               // nodes per gemm block

typedef unsigned long long ull;

// ---------------- scratch ----------------
__device__ float4 g_Y [N0 * 8];
__device__ float4 g_H [N0 * 8];
__device__ float4 g_G2[N1 * 8];
__device__ float4 g_G4[N1 * 8];
__device__ float4 g_G3[N2 * 8];
__device__ int   g_cnt[M];        // degree histogram / countdown cursors (0 at rest)
__device__ int   g_rowptr[M + 1];
__device__ int   g_eix[ETOT];
__device__ float g_dinv[M];
__device__ int   g_bsum[SCAN_NBLK];

// ---------------- f32x2 helpers ----------------
__device__ __forceinline__ ull pk2(float a, float b) {
    ull r; asm("mov.b64 %0, {%1, %2};" : "=l"(r) : "f"(a), "f"(b)); return r;
}
__device__ __forceinline__ ull fma2_(ull a, ull b, ull c) {
    ull d; asm("fma.rn.f32x2 %0, %1, %2, %3;" : "=l"(d) : "l"(a), "l"(b), "l"(c)); return d;
}
__device__ __forceinline__ float2 up2_(ull v) {
    float2 f; asm("mov.b64 {%0, %1}, %2;" : "=f"(f.x), "=f"(f.y) : "l"(v)); return f;
}
__device__ __forceinline__ float4 relu4(float4 v) {
    v.x = fmaxf(v.x, 0.f); v.y = fmaxf(v.y, 0.f);
    v.z = fmaxf(v.z, 0.f); v.w = fmaxf(v.w, 0.f);
    return v;
}

// ---------------- CSR build (4 launches) ----------------
__global__ void hist3(const int* __restrict__ d0, const int* __restrict__ d1,
                      const int* __restrict__ d2) {
    int t = blockIdx.x * blockDim.x + threadIdx.x;
    int g;
    if (t < E0) g = d0[t];
    else if (t < E0 + E1) g = GB1 + d1[t - E0];
    else if (t < ETOT) g = GB2 + d2[t - E0 - E1];
    else return;
    atomicAdd(&g_cnt[g], 1);
}

__global__ void scanA() {   // per-1024-chunk sums
    __shared__ int sb[256];
    int tid = threadIdx.x;
    int base = blockIdx.x * 1024 + tid * 4;
    int v = 0;
    #pragma unroll
    for (int k = 0; k < 4; k++) if (base + k < M) v += g_cnt[base + k];
    sb[tid] = v; __syncthreads();
    for (int off = 128; off; off >>= 1) {
        if (tid < off) sb[tid] += sb[tid + off];
        __syncthreads();
    }
    if (tid == 0) g_bsum[blockIdx.x] = sb[0];
}

// Fused scanB+scanC: each block reduces its prefix of block sums, then emits
// rowptr / dinv. g_cnt keeps the degree (used as countdown cursor in fill3).
__global__ void scanC2() {
    __shared__ int sb[256];
    __shared__ int s_pre;
    int tid = threadIdx.x;
    int partial = 0;
    for (int j = tid; j < blockIdx.x; j += 256) partial += g_bsum[j];
    sb[tid] = partial; __syncthreads();
    for (int off = 128; off; off >>= 1) {
        if (tid < off) sb[tid] += sb[tid + off];
        __syncthreads();
    }
    if (tid == 0) s_pre = sb[0];
    __syncthreads();

    int base = blockIdx.x * 1024 + tid * 4;
    int v[4], p[4], tsum = 0;
    #pragma unroll
    for (int k = 0; k < 4; k++) {
        v[k] = (base + k < M) ? g_cnt[base + k] : 0;
        p[k] = tsum; tsum += v[k];
    }
    sb[tid] = tsum; __syncthreads();
    for (int off = 1; off < 256; off <<= 1) {
        int t = (tid >= off) ? sb[tid - off] : 0;
        __syncthreads();
        sb[tid] += t;
        __syncthreads();
    }
    int off0 = s_pre + sb[tid] - tsum;
    #pragma unroll
    for (int k = 0; k < 4; k++) {
        int i = base + k;
        if (i < M) {
            g_rowptr[i] = off0 + p[k];
            g_dinv[i] = rsqrtf((float)v[k] + 1.0f);
        }
    }
    if (blockIdx.x == 0 && tid == 0) g_rowptr[M] = ETOT;
}

// Count-down fill: cursor = degree -> 0 (self-restoring for next run).
__global__ void fill3(const int* __restrict__ ei0, const int* __restrict__ ei1,
                      const int* __restrict__ ei2) {
    int t = blockIdx.x * blockDim.x + threadIdx.x;
    int g, s;
    if (t < E0)           { g = ei0[E0 + t];                 s = ei0[t]; }
    else if (t < E0 + E1) { int e = t - E0;      g = GB1 + ei1[E1 + e]; s = ei1[e]; }
    else if (t < ETOT)    { int e = t - E0 - E1; g = GB2 + ei2[E2 + e]; s = ei2[e]; }
    else return;
    int old = atomicSub(&g_cnt[g], 1);
    g_eix[g_rowptr[g] + old - 1] = s;
}

// ---------------- staged-x gemm (R9 verbatim) ----------------
#define GEMM_COMPUTE(n_)                                                  \
    __syncthreads();                                                      \
    int lane = tid & 31;                                                  \
    int sub = lane & 7, grp = lane >> 3;                                  \
    int lbase = (tid >> 5) * 16 + grp;                                    \
    ull a01[4] = {0, 0, 0, 0}, a23[4] = {0, 0, 0, 0};                     \
    _Pragma("unroll")                                                     \
    for (int g = 0; g < 8; g++) {                                         \
        ulonglong2 w0 = swu[(4 * g + 0) * 8 + sub];                       \
        ulonglong2 w1 = swu[(4 * g + 1) * 8 + sub];                       \
        ulonglong2 w2 = swu[(4 * g + 2) * 8 + sub];                       \
        ulonglong2 w3 = swu[(4 * g + 3) * 8 + sub];                       \
        _Pragma("unroll")                                                 \
        for (int j = 0; j < 4; j++) {                                     \
            float4 xv = sx[(lbase + 4 * j) * 9 + g];                      \
            a01[j] = fma2_(pk2(xv.x, xv.x), w0.x, a01[j]);                \
            a23[j] = fma2_(pk2(xv.x, xv.x), w0.y, a23[j]);                \
            a01[j] = fma2_(pk2(xv.y, xv.y), w1.x, a01[j]);                \
            a23[j] = fma2_(pk2(xv.y, xv.y), w1.y, a23[j]);                \
            a01[j] = fma2_(pk2(xv.z, xv.z), w2.x, a01[j]);                \
            a23[j] = fma2_(pk2(xv.z, xv.z), w2.y, a23[j]);                \
            a01[j] = fma2_(pk2(xv.w, xv.w), w3.x, a01[j]);                \
            a23[j] = fma2_(pk2(xv.w, xv.w), w3.y, a23[j]);                \
        }                                                                 \
    }                                                                     \
    _Pragma("unroll")                                                     \
    for (int j = 0; j < 4; j++) {                                         \
        int node = blockIdx.x * NPB + lbase + 4 * j;                      \
        if (node < n_) {                                                  \
            ulonglong2 r; r.x = a01[j]; r.y = a23[j];                     \
            ((ulonglong2*)Y)[node * 8 + sub] = r;                        \
        }                                                                 \
    }

__global__ void __launch_bounds__(256)
gemm_fc1(const float4* __restrict__ x,
         const float* __restrict__ fc1w, const float* __restrict__ fc1b,
         const float* __restrict__ w, float4* __restrict__ Y, int n)
{
    __shared__ ulonglong2 swu[256];
    __shared__ float4 sx[NPB * 9];
    __shared__ float4 sfw[32];
    __shared__ float4 sfb[8];
    int tid = threadIdx.x;
    swu[tid] = ((const ulonglong2*)w)[tid];
    if (tid < 32) sfw[tid] = ((const float4*)fc1w)[tid];
    if (tid < 8)  sfb[tid] = ((const float4*)fc1b)[tid];
    __syncthreads();
    int ln = tid >> 1;
    int nd = blockIdx.x * NPB + ln;
    int half = (tid & 1) * 4;
    if (nd < n) {
        float4 xin = x[nd];
        #pragma unroll
        for (int i = 0; i < 4; i++) {
            int q = half + i;
            float4 h = sfb[q];
            float4 r0 = sfw[q], r1 = sfw[8 + q], r2 = sfw[16 + q], r3 = sfw[24 + q];
            h.x += xin.x * r0.x + xin.y * r1.x + xin.z * r2.x + xin.w * r3.x;
            h.y += xin.x * r0.y + xin.y * r1.y + xin.z * r2.y + xin.w * r3.y;
            h.z += xin.x * r0.z + xin.y * r1.z + xin.z * r2.z + xin.w * r3.z;
            h.w += xin.x * r0.w + xin.y * r1.w + xin.z * r2.w + xin.w * r3.w;
            sx[ln * 9 + q] = relu4(h);
        }
    }
    GEMM_COMPUTE(n)
}

__global__ void __launch_bounds__(256)
gemm_down(const float4* __restrict__ in, const float* __restrict__ w,
          float4* __restrict__ Y, int n, int hy, int win)
{
    __shared__ ulonglong2 swu[256];
    __shared__ float4 sx[NPB * 9];
    int tid = threadIdx.x;
    swu[tid] = ((const ulonglong2*)w)[tid];
    int ln = tid >> 1;
    int nd = blockIdx.x * NPB + ln;
    int half = (tid & 1) * 4;
    if (nd < n) {
        int ix = nd / hy, iy = nd - ix * hy;
        const float4* src = in + ((2 * ix) * win + 2 * iy) * 8 + half;
        #pragma unroll
        for (int i = 0; i < 4; i++)
            sx[ln * 9 + half + i] = relu4(src[i]);
    }
    GEMM_COMPUTE(n)
}

__global__ void __launch_bounds__(256)
gemm_upadd(const float4* __restrict__ base, const float4* __restrict__ coarse,
           const float* __restrict__ w, float4* __restrict__ Y, int n, int hy)
{
    __shared__ ulonglong2 swu[256];
    __shared__ float4 sx[NPB * 9];
    int tid = threadIdx.x;
    swu[tid] = ((const ulonglong2*)w)[tid];
    int ln = tid >> 1;
    int nd = blockIdx.x * NPB + ln;
    int half = (tid & 1) * 4;
    if (nd < n) {
        int ix = nd / hy, iy = nd - ix * hy;
        int cn = (ix >> 1) * (hy >> 1) + (iy >> 1);
        const float4* bsrc = base + nd * 8 + half;
        const float4* csrc = coarse + cn * 8 + half;
        #pragma unroll
        for (int i = 0; i < 4; i++) {
            float4 xb = relu4(bsrc[i]);
            float4 xc = relu4(csrc[i]);
            sx[ln * 9 + half + i] =
                make_float4(xb.x + xc.x, xb.y + xc.y, xb.z + xc.z, xb.w + xc.w);
        }
    }
    GEMM_COMPUTE(n)
}

// ---------------- dual-node interleaved gather ----------------
// 8 threads per node PAIR; two independent edge loops interleaved -> 2 chains
// in flight per thread, no masking overhead.
__device__ __forceinline__ void gather_pair(
    const ulonglong2* __restrict__ Yp, int n0, int sub, int gb,
    const float* __restrict__ bias,
    ulonglong2& o0, ulonglong2& o1)
{
    int b0 = g_rowptr[gb + n0];
    int e0 = g_rowptr[gb + n0 + 1];
    int e1 = g_rowptr[gb + n0 + 2];
    float dd0 = g_dinv[gb + n0], dd1 = g_dinv[gb + n0 + 1];
    ull a01 = 0, a23 = 0, c01 = 0, c23 = 0;
    int p0 = b0, p1 = e0;
    while (p0 < e0 && p1 < e1) {
        int s0 = g_eix[p0], s1 = g_eix[p1];
        float m0 = g_dinv[gb + s0], m1 = g_dinv[gb + s1];
        ulonglong2 v0 = Yp[s0 * 8 + sub];
        ulonglong2 v1 = Yp[s1 * 8 + sub];
        a01 = fma2_(v0.x, pk2(m0, m0), a01);
        a23 = fma2_(v0.y, pk2(m0, m0), a23);
        c01 = fma2_(v1.x, pk2(m1, m1), c01);
        c23 = fma2_(v1.y, pk2(m1, m1), c23);
        p0++; p1++;
    }
    for (; p0 < e0; p0++) {
        int s = g_eix[p0];
        float m = g_dinv[gb + s];
        ulonglong2 v = Yp[s * 8 + sub];
        a01 = fma2_(v.x, pk2(m, m), a01);
        a23 = fma2_(v.y, pk2(m, m), a23);
    }
    for (; p1 < e1; p1++) {
        int s = g_eix[p1];
        float m = g_dinv[gb + s];
        ulonglong2 v = Yp[s * 8 + sub];
        c01 = fma2_(v.x, pk2(m, m), c01);
        c23 = fma2_(v.y, pk2(m, m), c23);
    }
    ulonglong2 s0r = Yp[n0 * 8 + sub];
    ulonglong2 s1r = Yp[(n0 + 1) * 8 + sub];
    float4 bb = ((const float4*)bias)[sub];
    ull bb01 = pk2(bb.x, bb.y), bb23 = pk2(bb.z, bb.w);
    ull d0p = pk2(dd0, dd0), d1p = pk2(dd1, dd1);
    o0.x = fma2_(fma2_(s0r.x, d0p, a01), d0p, bb01);
    o0.y = fma2_(fma2_(s0r.y, d0p, a23), d0p, bb23);
    o1.x = fma2_(fma2_(s1r.x, d1p, c01), d1p, bb01);
    o1.y = fma2_(fma2_(s1r.y, d1p, c23), d1p, bb23);
}

__global__ void gather(const float4* __restrict__ Yf,
                       const float* __restrict__ bias,
                       float4* __restrict__ OUT, int n, int gb)
{
    int t = blockIdx.x * blockDim.x + threadIdx.x;
    int grp = t >> 3, sub = t & 7;
    int n0 = grp * 2;
    if (n0 >= n) return;
    ulonglong2 o0, o1;
    gather_pair((const ulonglong2*)Yf, n0, sub, gb, bias, o0, o1);
    ((ulonglong2*)OUT)[n0 * 8 + sub] = o0;
    ((ulonglong2*)OUT)[(n0 + 1) * 8 + sub] = o1;
}

__global__ void gather_fc2(const float4* __restrict__ Yf,
                           const float* __restrict__ bias,
                           const float* __restrict__ w2, const float* __restrict__ b2,
                           float* __restrict__ out, int n)
{
    __shared__ float sw[96];
    int tid = threadIdx.x;
    if (tid < 96) sw[tid] = w2[tid];
    __syncthreads();
    int t = blockIdx.x * blockDim.x + tid;
    int grp = t >> 3, sub = t & 7;
    int n0 = grp * 2;
    if (n0 >= n) return;
    ulonglong2 o0, o1;
    gather_pair((const ulonglong2*)Yf, n0, sub, 0, bias, o0, o1);
    int c = 4 * sub;
    #pragma unroll
    for (int j = 0; j < 2; j++) {
        ulonglong2 o = j == 0 ? o0 : o1;
        float2 v01 = up2_(o.x), v23 = up2_(o.y);
        float4 v = relu4(make_float4(v01.x, v01.y, v23.x, v23.y));
        float p0 = v.x*sw[(c+0)*3+0] + v.y*sw[(c+1)*3+0] + v.z*sw[(c+2)*3+0] + v.w*sw[(c+3)*3+0];
        float p1 = v.x*sw[(c+0)*3+1] + v.y*sw[(c+1)*3+1] + v.z*sw[(c+2)*3+1] + v.w*sw[(c+3)*3+1];
        float p2 = v.x*sw[(c+0)*3+2] + v.y*sw[(c+1)*3+2] + v.z*sw[(c+2)*3+2] + v.w*sw[(c+3)*3+2];
        #pragma unroll
        for (int off = 4; off; off >>= 1) {
            p0 += __shfl_down_sync(0xffffffffu, p0, off, 8);
            p1 += __shfl_down_sync(0xffffffffu, p1, off, 8);
            p2 += __shfl_down_sync(0xffffffffu, p2, off, 8);
        }
        if (sub == 0) {
            int node = n0 + j;
            out[node * 3 + 0] = p0 + __ldg(&b2[0]);
            out[node * 3 + 1] = p1 + __ldg(&b2[1]);
            out[node * 3 + 2] = p2 + __ldg(&b2[2]);
        }
    }
}

// ---------------------------------------------------------------------------
static inline int ceil_div(int a, int b) { return (a + b - 1) / b; }

extern "C" void kernel_launch(void* const* d_in, const int* in_sizes, int n_in,
                              void* d_out, int out_size) {
    const float* x     = (const float*)d_in[0];
    const float* fc1_w = (const float*)d_in[1];
    const float* fc1_b = (const float*)d_in[2];
    const float* w1 = (const float*)d_in[3];  const float* b1 = (const float*)d_in[4];
    const float* w2 = (const float*)d_in[5];  const float* b2 = (const float*)d_in[6];
    const float* w3 = (const float*)d_in[7];  const float* b3 = (const float*)d_in[8];
    const float* w4 = (const float*)d_in[9];  const float* b4 = (const float*)d_in[10];
    const float* w5 = (const float*)d_in[11]; const float* b5 = (const float*)d_in[12];
    const float* fc2_w = (const float*)d_in[13];
    const float* fc2_b = (const float*)d_in[14];
    const int* ei0 = (const int*)d_in[18];
    const int* ei1 = (const int*)d_in[19];
    const int* ei2 = (const int*)d_in[20];
    float* out = (float*)d_out;

    float4 *Y, *H, *G2, *G4, *G3;
    cudaGetSymbolAddress((void**)&Y,  g_Y);
    cudaGetSymbolAddress((void**)&H,  g_H);
    cudaGetSymbolAddress((void**)&G2, g_G2);
    cudaGetSymbolAddress((void**)&G4, g_G4);
    cudaGetSymbolAddress((void**)&G3, g_G3);

    const int TB = 256;

    // 0-2: CSR build (cnt is 0 at rest; hist -> scanA -> fused scan)
    hist3<<<ceil_div(ETOT, TB), TB>>>(ei0 + E0, ei1 + E1, ei2 + E2);
    scanA<<<SCAN_NBLK, 256>>>();
    scanC2<<<SCAN_NBLK, 256>>>();
    // 3: GCN1 gemm (CSR-independent; profiled launch)
    gemm_fc1<<<ceil_div(N0, NPB), TB>>>((const float4*)x, fc1_w, fc1_b, w1, Y, N0);
    // 4: CSR fill (count-down cursors restore cnt to 0)
    fill3<<<ceil_div(ETOT, TB), TB>>>(ei0, ei1, ei2);

    // 5: GCN1 gather
    gather<<<N0 / 64, TB>>>(Y, b1, H, N0, 0);

    // 6-7: GCN2
    gemm_down<<<ceil_div(N1, NPB), TB>>>(H, w2, Y, N1, NYg / 2, NYg);
    gather<<<N1 / 64, TB>>>(Y, b2, G2, N1, GB1);

    // 8-9: GCN3
    gemm_down<<<ceil_div(N2, NPB), TB>>>(G2, w3, Y, N2, NYg / 4, NYg / 2);
    gather<<<N2 / 64, TB>>>(Y, b3, G3, N2, GB2);

    // 10-11: GCN4
    gemm_upadd<<<ceil_div(N1, NPB), TB>>>(G2, G3, w4, Y, N1, NYg / 2);
    gather<<<N1 / 64, TB>>>(Y, b4, G4, N1, GB1);

    // 12-13: GCN5 + fc2
    gemm_upadd<<<ceil_div(N0, NPB), TB>>>(H, G4, w5, Y, N0, NYg);
    gather_fc2<<<N0 / 64, TB>>>(Y, b5, fc2_w, fc2_b, out, N0);

    (void)in_sizes; (void)n_in; (void)out_size;
}

// round 13
// speedup vs baseline: 1.1790x; 1.0918x over previous
#include <cuda_runtime.h>

// Net_multi_11390253269716: 3-level GCN U-Net, 784x480 grid, C=32.
// R12: R9 verbatim (238us, rel 6e-8) + gemm_fc1 forked onto a second stream
//      to overlap with the CSR build (independent chains, different pipes),
//      and R5-proven fused scanC2 (5-launch build).

#define NXg 784
#define NYg 480
#define C 32
#define N0 (NXg * NYg)        // 376320
#define N1 (N0 / 4)           // 94080
#define N2 (N0 / 16)          // 23520
#define E0 (4 * N0)
#define E1 (4 * N1)
#define E2 (4 * N2)
#define ETOT (E0 + E1 + E2)   // 1975680
#define M (N0 + N1 + N2)      // 493920
#define GB1 N0
#define GB2 (N0 + N1)
#define SCAN_NBLK ((M + 1023) / 1024)   // 483
#define NPB 128               // nodes per gemm block

typedef unsigned long long ull;

// ---------------- scratch ----------------
__device__ float4 g_Y [N0 * 8];
__device__ float4 g_H [N0 * 8];
__device__ float4 g_G2[N1 * 8];
__device__ float4 g_G4[N1 * 8];
__device__ float4 g_G3[N2 * 8];
__device__ int   g_cnt[M];
__device__ int   g_rowptr[M + 1];
__device__ int   g_eix[ETOT];
__device__ float g_dinv[M];
__device__ int   g_bsum[SCAN_NBLK];

// ---------------- f32x2 helpers ----------------
__device__ __forceinline__ ull pk2(float a, float b) {
    ull r; asm("mov.b64 %0, {%1, %2};" : "=l"(r) : "f"(a), "f"(b)); return r;
}
__device__ __forceinline__ ull fma2_(ull a, ull b, ull c) {
    ull d; asm("fma.rn.f32x2 %0, %1, %2, %3;" : "=l"(d) : "l"(a), "l"(b), "l"(c)); return d;
}
__device__ __forceinline__ float2 up2_(ull v) {
    float2 f; asm("mov.b64 {%0, %1}, %2;" : "=f"(f.x), "=f"(f.y) : "l"(v)); return f;
}
__device__ __forceinline__ float4 relu4(float4 v) {
    v.x = fmaxf(v.x, 0.f); v.y = fmaxf(v.y, 0.f);
    v.z = fmaxf(v.z, 0.f); v.w = fmaxf(v.w, 0.f);
    return v;
}

// ---------------- CSR build (5 launches, R5-proven) ----------------
__global__ void zero_cnt() {
    int i = blockIdx.x * blockDim.x + threadIdx.x;
    if (i < M) g_cnt[i] = 0;
}

__global__ void hist3(const int* __restrict__ d0, const int* __restrict__ d1,
                      const int* __restrict__ d2) {
    int t = blockIdx.x * blockDim.x + threadIdx.x;
    int g;
    if (t < E0) g = d0[t];
    else if (t < E0 + E1) g = GB1 + d1[t - E0];
    else if (t < ETOT) g = GB2 + d2[t - E0 - E1];
    else return;
    atomicAdd(&g_cnt[g], 1);
}

__global__ void scanA() {   // per-1024-chunk sums
    __shared__ int sb[256];
    int tid = threadIdx.x;
    int base = blockIdx.x * 1024 + tid * 4;
    int v = 0;
    #pragma unroll
    for (int k = 0; k < 4; k++) if (base + k < M) v += g_cnt[base + k];
    sb[tid] = v; __syncthreads();
    for (int off = 128; off; off >>= 1) {
        if (tid < off) sb[tid] += sb[tid + off];
        __syncthreads();
    }
    if (tid == 0) g_bsum[blockIdx.x] = sb[0];
}

// Fused scanB+scanC (R5-proven): each block reduces its prefix of block sums,
// then emits rowptr / dinv / zeroed cursors.
__global__ void scanC2() {
    __shared__ int sb[256];
    __shared__ int s_pre;
    int tid = threadIdx.x;
    int partial = 0;
    for (int j = tid; j < blockIdx.x; j += 256) partial += g_bsum[j];
    sb[tid] = partial; __syncthreads();
    for (int off = 128; off; off >>= 1) {
        if (tid < off) sb[tid] += sb[tid + off];
        __syncthreads();
    }
    if (tid == 0) s_pre = sb[0];
    __syncthreads();

    int base = blockIdx.x * 1024 + tid * 4;
    int v[4], p[4], tsum = 0;
    #pragma unroll
    for (int k = 0; k < 4; k++) {
        v[k] = (base + k < M) ? g_cnt[base + k] : 0;
        p[k] = tsum; tsum += v[k];
    }
    sb[tid] = tsum; __syncthreads();
    for (int off = 1; off < 256; off <<= 1) {
        int t = (tid >= off) ? sb[tid - off] : 0;
        __syncthreads();
        sb[tid] += t;
        __syncthreads();
    }
    int off0 = s_pre + sb[tid] - tsum;
    #pragma unroll
    for (int k = 0; k < 4; k++) {
        int i = base + k;
        if (i < M) {
            g_rowptr[i] = off0 + p[k];
            g_dinv[i] = rsqrtf((float)v[k] + 1.0f);
            g_cnt[i] = 0;
        }
    }
    if (blockIdx.x == 0 && tid == 0) g_rowptr[M] = ETOT;
}

__global__ void fill3(const int* __restrict__ ei0, const int* __restrict__ ei1,
                      const int* __restrict__ ei2) {
    int t = blockIdx.x * blockDim.x + threadIdx.x;
    int g, s;
    if (t < E0)           { g = ei0[E0 + t];                 s = ei0[t]; }
    else if (t < E0 + E1) { int e = t - E0;      g = GB1 + ei1[E1 + e]; s = ei1[e]; }
    else if (t < ETOT)    { int e = t - E0 - E1; g = GB2 + ei2[E2 + e]; s = ei2[e]; }
    else return;
    int pos = g_rowptr[g] + atomicAdd(&g_cnt[g], 1);
    g_eix[pos] = s;
}

// ---------------- staged-x gemm (R9 verbatim) ----------------
#define GEMM_COMPUTE(n_)                                                  \
    __syncthreads();                                                      \
    int lane = tid & 31;                                                  \
    int sub = lane & 7, grp = lane >> 3;                                  \
    int lbase = (tid >> 5) * 16 + grp;                                    \
    ull a01[4] = {0, 0, 0, 0}, a23[4] = {0, 0, 0, 0};                     \
    _Pragma("unroll")                                                     \
    for (int g = 0; g < 8; g++) {                                         \
        ulonglong2 w0 = swu[(4 * g + 0) * 8 + sub];                       \
        ulonglong2 w1 = swu[(4 * g + 1) * 8 + sub];                       \
        ulonglong2 w2 = swu[(4 * g + 2) * 8 + sub];                       \
        ulonglong2 w3 = swu[(4 * g + 3) * 8 + sub];                       \
        _Pragma("unroll")                                                 \
        for (int j = 0; j < 4; j++) {                                     \
            float4 xv = sx[(lbase + 4 * j) * 9 + g];                      \
            a01[j] = fma2_(pk2(xv.x, xv.x), w0.x, a01[j]);                \
            a23[j] = fma2_(pk2(xv.x, xv.x), w0.y, a23[j]);                \
            a01[j] = fma2_(pk2(xv.y, xv.y), w1.x, a01[j]);                \
            a23[j] = fma2_(pk2(xv.y, xv.y), w1.y, a23[j]);                \
            a01[j] = fma2_(pk2(xv.z, xv.z), w2.x, a01[j]);                \
            a23[j] = fma2_(pk2(xv.z, xv.z), w2.y, a23[j]);                \
            a01[j] = fma2_(pk2(xv.w, xv.w), w3.x, a01[j]);                \
            a23[j] = fma2_(pk2(xv.w, xv.w), w3.y, a23[j]);                \
        }                                                                 \
    }                                                                     \
    _Pragma("unroll")                                                     \
    for (int j = 0; j < 4; j++) {                                         \
        int node = blockIdx.x * NPB + lbase + 4 * j;                      \
        if (node < n_) {                                                  \
            ulonglong2 r; r.x = a01[j]; r.y = a23[j];                     \
            ((ulonglong2*)Y)[node * 8 + sub] = r;                        \
        }                                                                 \
    }

__global__ void __launch_bounds__(256)
gemm_fc1(const float4* __restrict__ x,
         const float* __restrict__ fc1w, const float* __restrict__ fc1b,
         const float* __restrict__ w, float4* __restrict__ Y, int n)
{
    __shared__ ulonglong2 swu[256];
    __shared__ float4 sx[NPB * 9];
    __shared__ float4 sfw[32];
    __shared__ float4 sfb[8];
    int tid = threadIdx.x;
    swu[tid] = ((const ulonglong2*)w)[tid];
    if (tid < 32) sfw[tid] = ((const float4*)fc1w)[tid];
    if (tid < 8)  sfb[tid] = ((const float4*)fc1b)[tid];
    __syncthreads();
    int ln = tid >> 1;
    int nd = blockIdx.x * NPB + ln;
    int half = (tid & 1) * 4;
    if (nd < n) {
        float4 xin = x[nd];
        #pragma unroll
        for (int i = 0; i < 4; i++) {
            int q = half + i;
            float4 h = sfb[q];
            float4 r0 = sfw[q], r1 = sfw[8 + q], r2 = sfw[16 + q], r3 = sfw[24 + q];
            h.x += xin.x * r0.x + xin.y * r1.x + xin.z * r2.x + xin.w * r3.x;
            h.y += xin.x * r0.y + xin.y * r1.y + xin.z * r2.y + xin.w * r3.y;
            h.z += xin.x * r0.z + xin.y * r1.z + xin.z * r2.z + xin.w * r3.z;
            h.w += xin.x * r0.w + xin.y * r1.w + xin.z * r2.w + xin.w * r3.w;
            sx[ln * 9 + q] = relu4(h);
        }
    }
    GEMM_COMPUTE(n)
}

__global__ void __launch_bounds__(256)
gemm_down(const float4* __restrict__ in, const float* __restrict__ w,
          float4* __restrict__ Y, int n, int hy, int win)
{
    __shared__ ulonglong2 swu[256];
    __shared__ float4 sx[NPB * 9];
    int tid = threadIdx.x;
    swu[tid] = ((const ulonglong2*)w)[tid];
    int ln = tid >> 1;
    int nd = blockIdx.x * NPB + ln;
    int half = (tid & 1) * 4;
    if (nd < n) {
        int ix = nd / hy, iy = nd - ix * hy;
        const float4* src = in + ((2 * ix) * win + 2 * iy) * 8 + half;
        #pragma unroll
        for (int i = 0; i < 4; i++)
            sx[ln * 9 + half + i] = relu4(src[i]);
    }
    GEMM_COMPUTE(n)
}

__global__ void __launch_bounds__(256)
gemm_upadd(const float4* __restrict__ base, const float4* __restrict__ coarse,
           const float* __restrict__ w, float4* __restrict__ Y, int n, int hy)
{
    __shared__ ulonglong2 swu[256];
    __shared__ float4 sx[NPB * 9];
    int tid = threadIdx.x;
    swu[tid] = ((const ulonglong2*)w)[tid];
    int ln = tid >> 1;
    int nd = blockIdx.x * NPB + ln;
    int half = (tid & 1) * 4;
    if (nd < n) {
        int ix = nd / hy, iy = nd - ix * hy;
        int cn = (ix >> 1) * (hy >> 1) + (iy >> 1);
        const float4* bsrc = base + nd * 8 + half;
        const float4* csrc = coarse + cn * 8 + half;
        #pragma unroll
        for (int i = 0; i < 4; i++) {
            float4 xb = relu4(bsrc[i]);
            float4 xc = relu4(csrc[i]);
            sx[ln * 9 + half + i] =
                make_float4(xb.x + xc.x, xb.y + xc.y, xb.z + xc.z, xb.w + xc.w);
        }
    }
    GEMM_COMPUTE(n)
}

// ---------------- gather (R9 verbatim) ----------------
__device__ __forceinline__ void gather_acc(
    const ulonglong2* __restrict__ Y, int node, int sub, int gbase,
    const float* __restrict__ bias, ull& a01, ull& a23)
{
    float di = g_dinv[gbase + node];
    int beg = g_rowptr[gbase + node];
    int end = g_rowptr[gbase + node + 1];
    float4 bb = ((const float4*)bias)[sub];
    float s2 = di * di;
    ulonglong2 y = Y[node * 8 + sub];
    ull s22 = pk2(s2, s2);
    a01 = fma2_(y.x, s22, pk2(bb.x, bb.y));
    a23 = fma2_(y.y, s22, pk2(bb.z, bb.w));
    for (int p = beg; p < end; p++) {
        int s = g_eix[p];
        float nm = g_dinv[gbase + s] * di;
        ulonglong2 v = Y[s * 8 + sub];
        ull nn = pk2(nm, nm);
        a01 = fma2_(v.x, nn, a01);
        a23 = fma2_(v.y, nn, a23);
    }
}

__global__ void gather(const float4* __restrict__ Yf,
                       const float* __restrict__ bias,
                       float4* __restrict__ OUT, int n, int gbase)
{
    int t = blockIdx.x * blockDim.x + threadIdx.x;
    int node = t >> 3, sub = t & 7;
    if (node >= n) return;
    ull a01, a23;
    gather_acc((const ulonglong2*)Yf, node, sub, gbase, bias, a01, a23);
    ulonglong2 r; r.x = a01; r.y = a23;
    ((ulonglong2*)OUT)[node * 8 + sub] = r;
}

__global__ void gather_fc2(const float4* __restrict__ Yf,
                           const float* __restrict__ bias,
                           const float* __restrict__ w2, const float* __restrict__ b2,
                           float* __restrict__ out, int n)
{
    __shared__ float sw[96];
    int tid = threadIdx.x;
    if (tid < 96) sw[tid] = w2[tid];
    __syncthreads();
    int t = blockIdx.x * blockDim.x + tid;
    int node = t >> 3, sub = t & 7;
    if (node >= n) return;
    ull a01, a23;
    gather_acc((const ulonglong2*)Yf, node, sub, 0, bias, a01, a23);
    float2 v01 = up2_(a01), v23 = up2_(a23);
    float4 v = relu4(make_float4(v01.x, v01.y, v23.x, v23.y));
    int c = 4 * sub;
    float p0 = v.x * sw[(c+0)*3+0] + v.y * sw[(c+1)*3+0] + v.z * sw[(c+2)*3+0] + v.w * sw[(c+3)*3+0];
    float p1 = v.x * sw[(c+0)*3+1] + v.y * sw[(c+1)*3+1] + v.z * sw[(c+2)*3+1] + v.w * sw[(c+3)*3+1];
    float p2 = v.x * sw[(c+0)*3+2] + v.y * sw[(c+1)*3+2] + v.z * sw[(c+2)*3+2] + v.w * sw[(c+3)*3+2];
    #pragma unroll
    for (int off = 4; off; off >>= 1) {
        p0 += __shfl_down_sync(0xffffffffu, p0, off, 8);
        p1 += __shfl_down_sync(0xffffffffu, p1, off, 8);
        p2 += __shfl_down_sync(0xffffffffu, p2, off, 8);
    }
    if (sub == 0) {
        out[node * 3 + 0] = p0 + __ldg(&b2[0]);
        out[node * 3 + 1] = p1 + __ldg(&b2[1]);
        out[node * 3 + 2] = p2 + __ldg(&b2[2]);
    }
}

// ---------------------------------------------------------------------------
static inline int ceil_div(int a, int b) { return (a + b - 1) / b; }

static cudaStream_t g_s2 = 0;
static cudaEvent_t  g_ev1 = 0, g_ev2 = 0;

extern "C" void kernel_launch(void* const* d_in, const int* in_sizes, int n_in,
                              void* d_out, int out_size) {
    const float* x     = (const float*)d_in[0];
    const float* fc1_w = (const float*)d_in[1];
    const float* fc1_b = (const float*)d_in[2];
    const float* w1 = (const float*)d_in[3];  const float* b1 = (const float*)d_in[4];
    const float* w2 = (const float*)d_in[5];  const float* b2 = (const float*)d_in[6];
    const float* w3 = (const float*)d_in[7];  const float* b3 = (const float*)d_in[8];
    const float* w4 = (const float*)d_in[9];  const float* b4 = (const float*)d_in[10];
    const float* w5 = (const float*)d_in[11]; const float* b5 = (const float*)d_in[12];
    const float* fc2_w = (const float*)d_in[13];
    const float* fc2_b = (const float*)d_in[14];
    const int* ei0 = (const int*)d_in[18];
    const int* ei1 = (const int*)d_in[19];
    const int* ei2 = (const int*)d_in[20];
    float* out = (float*)d_out;

    float4 *Y, *H, *G2, *G4, *G3;
    cudaGetSymbolAddress((void**)&Y,  g_Y);
    cudaGetSymbolAddress((void**)&H,  g_H);
    cudaGetSymbolAddress((void**)&G2, g_G2);
    cudaGetSymbolAddress((void**)&G4, g_G4);
    cudaGetSymbolAddress((void**)&G3, g_G3);

    if (!g_s2) {
        cudaStreamCreateWithFlags(&g_s2, cudaStreamNonBlocking);
        cudaEventCreateWithFlags(&g_ev1, cudaEventDisableTiming);
        cudaEventCreateWithFlags(&g_ev2, cudaEventDisableTiming);
    }

    const int TB = 256;

    // Fork: gemm_fc1 (CSR-independent) runs on side stream, overlapped with
    // the CSR build on the main stream.
    cudaEventRecord(g_ev1, 0);
    cudaStreamWaitEvent(g_s2, g_ev1, 0);
    gemm_fc1<<<ceil_div(N0, NPB), TB, 0, g_s2>>>((const float4*)x, fc1_w, fc1_b,
                                                 w1, Y, N0);
    cudaEventRecord(g_ev2, g_s2);

    // CSR build on main stream (5 launches)
    zero_cnt<<<ceil_div(M, TB), TB>>>();
    hist3<<<ceil_div(ETOT, TB), TB>>>(ei0 + E0, ei1 + E1, ei2 + E2);
    scanA<<<SCAN_NBLK, 256>>>();
    scanC2<<<SCAN_NBLK, 256>>>();
    fill3<<<ceil_div(ETOT, TB), TB>>>(ei0, ei1, ei2);

    // Join: gather1 needs both fill3 (main) and gemm_fc1 (side)
    cudaStreamWaitEvent(0, g_ev2, 0);

    // GCN1 gather
    gather<<<N0 / 32, TB>>>(Y, b1, H, N0, 0);

    // GCN2
    gemm_down<<<ceil_div(N1, NPB), TB>>>(H, w2, Y, N1, NYg / 2, NYg);
    gather<<<N1 / 32, TB>>>(Y, b2, G2, N1, GB1);

    // GCN3
    gemm_down<<<ceil_div(N2, NPB), TB>>>(G2, w3, Y, N2, NYg / 4, NYg / 2);
    gather<<<N2 / 32, TB>>>(Y, b3, G3, N2, GB2);

    // GCN4
    gemm_upadd<<<ceil_div(N1, NPB), TB>>>(G2, G3, w4, Y, N1, NYg / 2);
    gather<<<N1 / 32, TB>>>(Y, b4, G4, N1, GB1);

    // GCN5 + fc2
    gemm_upadd<<<ceil_div(N0, NPB), TB>>>(H, G4, w5, Y, N0, NYg);
    gather_fc2<<<N0 / 32, TB>>>(Y, b5, fc2_w, fc2_b, out, N0);

    (void)in_sizes; (void)n_in; (void)out_size;
}

// round 15
// speedup vs baseline: 1.2014x; 1.0190x over previous
#include <cuda_runtime.h>

// Net_multi_11390253269716: 3-level GCN U-Net, 784x480 grid, C=32.
// R13: R12 base + split-level CSR build. Level-0 CSR on main stream (gather1
//      starts ~10us earlier); level-1/2 CSR + gemm_fc1 on side stream,
//      hidden under gather1. Compute kernels R12-verbatim.

#define NXg 784
#define NYg 480
#define C 32
#define N0 (NXg * NYg)        // 376320
#define N1 (N0 / 4)           // 94080
#define N2 (N0 / 16)          // 23520
#define E0 (4 * N0)
#define E1 (4 * N1)
#define E2 (4 * N2)
#define E12 (E1 + E2)
#define ETOT (E0 + E1 + E2)   // 1975680
#define M (N0 + N1 + N2)      // 493920
#define M12 (N1 + N2)         // 117600
#define GB1 N0
#define GB2 (N0 + N1)
#define NBLK0 ((N0 + 1023) / 1024)    // 368
#define NBLK12 ((M12 + 1023) / 1024)  // 115
#define NPB 128               // nodes per gemm block

typedef unsigned long long ull;

// ---------------- scratch ----------------
__device__ float4 g_Y [N0 * 8];
__device__ float4 g_H [N0 * 8];
__device__ float4 g_G2[N1 * 8];
__device__ float4 g_G4[N1 * 8];
__device__ float4 g_G3[N2 * 8];
__device__ int   g_cnt[M];
__device__ int   g_rowptr[M + 1];
__device__ int   g_eix[ETOT];
__device__ float g_dinv[M];
__device__ int   g_bsum0[NBLK0];
__device__ int   g_bsum12[NBLK12];

// ---------------- f32x2 helpers ----------------
__device__ __forceinline__ ull pk2(float a, float b) {
    ull r; asm("mov.b64 %0, {%1, %2};" : "=l"(r) : "f"(a), "f"(b)); return r;
}
__device__ __forceinline__ ull fma2_(ull a, ull b, ull c) {
    ull d; asm("fma.rn.f32x2 %0, %1, %2, %3;" : "=l"(d) : "l"(a), "l"(b), "l"(c)); return d;
}
__device__ __forceinline__ float2 up2_(ull v) {
    float2 f; asm("mov.b64 {%0, %1}, %2;" : "=f"(f.x), "=f"(f.y) : "l"(v)); return f;
}
__device__ __forceinline__ float4 relu4(float4 v) {
    v.x = fmaxf(v.x, 0.f); v.y = fmaxf(v.y, 0.f);
    v.z = fmaxf(v.z, 0.f); v.w = fmaxf(v.w, 0.f);
    return v;
}

// ---------------- CSR build (split by level) ----------------
__global__ void zero_cnt() {
    int i = blockIdx.x * blockDim.x + threadIdx.x;
    if (i < M) g_cnt[i] = 0;
}

__global__ void hist0(const int* __restrict__ d0) {
    int t = blockIdx.x * blockDim.x + threadIdx.x;
    if (t < E0) atomicAdd(&g_cnt[d0[t]], 1);
}

__global__ void hist12(const int* __restrict__ d1, const int* __restrict__ d2) {
    int t = blockIdx.x * blockDim.x + threadIdx.x;
    if (t < E1) atomicAdd(&g_cnt[GB1 + d1[t]], 1);
    else if (t < E12) atomicAdd(&g_cnt[GB2 + d2[t - E1]], 1);
}

// per-1024-chunk sums over g_cnt[start, start+nn)
__global__ void scanA_r(int* bsum, int start, int nn) {
    __shared__ int sb[256];
    int tid = threadIdx.x;
    int base = blockIdx.x * 1024 + tid * 4;
    int v = 0;
    #pragma unroll
    for (int k = 0; k < 4; k++)
        if (base + k < nn) v += g_cnt[start + base + k];
    sb[tid] = v; __syncthreads();
    for (int off = 128; off; off >>= 1) {
        if (tid < off) sb[tid] += sb[tid + off];
        __syncthreads();
    }
    if (tid == 0) bsum[blockIdx.x] = sb[0];
}

// fused scanB+scanC over a range: rowptr[start+i] = rp_base + prefix,
// dinv, zero cursors; block0/tid0 also writes rowptr[start+nn] = rp_end.
__global__ void scanC2_r(const int* __restrict__ bsum, int start, int nn,
                         int rp_base, int rp_end) {
    __shared__ int sb[256];
    __shared__ int s_pre;
    int tid = threadIdx.x;
    int partial = 0;
    for (int j = tid; j < blockIdx.x; j += 256) partial += bsum[j];
    sb[tid] = partial; __syncthreads();
    for (int off = 128; off; off >>= 1) {
        if (tid < off) sb[tid] += sb[tid + off];
        __syncthreads();
    }
    if (tid == 0) s_pre = sb[0];
    __syncthreads();

    int base = blockIdx.x * 1024 + tid * 4;
    int v[4], p[4], tsum = 0;
    #pragma unroll
    for (int k = 0; k < 4; k++) {
        v[k] = (base + k < nn) ? g_cnt[start + base + k] : 0;
        p[k] = tsum; tsum += v[k];
    }
    sb[tid] = tsum; __syncthreads();
    for (int off = 1; off < 256; off <<= 1) {
        int t = (tid >= off) ? sb[tid - off] : 0;
        __syncthreads();
        sb[tid] += t;
        __syncthreads();
    }
    int off0 = rp_base + s_pre + sb[tid] - tsum;
    #pragma unroll
    for (int k = 0; k < 4; k++) {
        int i = base + k;
        if (i < nn) {
            g_rowptr[start + i] = off0 + p[k];
            g_dinv[start + i] = rsqrtf((float)v[k] + 1.0f);
            g_cnt[start + i] = 0;
        }
    }
    if (blockIdx.x == 0 && tid == 0) g_rowptr[start + nn] = rp_end;
}

__global__ void fill0(const int* __restrict__ ei0) {
    int t = blockIdx.x * blockDim.x + threadIdx.x;
    if (t >= E0) return;
    int g = ei0[E0 + t];
    int pos = g_rowptr[g] + atomicAdd(&g_cnt[g], 1);
    g_eix[pos] = ei0[t];
}

__global__ void fill12(const int* __restrict__ ei1, const int* __restrict__ ei2) {
    int t = blockIdx.x * blockDim.x + threadIdx.x;
    int g, s;
    if (t < E1)       { g = GB1 + ei1[E1 + t];              s = ei1[t]; }
    else if (t < E12) { int e = t - E1; g = GB2 + ei2[E2 + e]; s = ei2[e]; }
    else return;
    int pos = g_rowptr[g] + atomicAdd(&g_cnt[g], 1);
    g_eix[pos] = s;
}

// ---------------- staged-x gemm (R9/R12 verbatim) ----------------
#define GEMM_COMPUTE(n_)                                                  \
    __syncthreads();                                                      \
    int lane = tid & 31;                                                  \
    int sub = lane & 7, grp = lane >> 3;                                  \
    int lbase = (tid >> 5) * 16 + grp;                                    \
    ull a01[4] = {0, 0, 0, 0}, a23[4] = {0, 0, 0, 0};                     \
    _Pragma("unroll")                                                     \
    for (int g = 0; g < 8; g++) {                                         \
        ulonglong2 w0 = swu[(4 * g + 0) * 8 + sub];                       \
        ulonglong2 w1 = swu[(4 * g + 1) * 8 + sub];                       \
        ulonglong2 w2 = swu[(4 * g + 2) * 8 + sub];                       \
        ulonglong2 w3 = swu[(4 * g + 3) * 8 + sub];                       \
        _Pragma("unroll")                                                 \
        for (int j = 0; j < 4; j++) {                                     \
            float4 xv = sx[(lbase + 4 * j) * 9 + g];                      \
            a01[j] = fma2_(pk2(xv.x, xv.x), w0.x, a01[j]);                \
            a23[j] = fma2_(pk2(xv.x, xv.x), w0.y, a23[j]);                \
            a01[j] = fma2_(pk2(xv.y, xv.y), w1.x, a01[j]);                \
            a23[j] = fma2_(pk2(xv.y, xv.y), w1.y, a23[j]);                \
            a01[j] = fma2_(pk2(xv.z, xv.z), w2.x, a01[j]);                \
            a23[j] = fma2_(pk2(xv.z, xv.z), w2.y, a23[j]);                \
            a01[j] = fma2_(pk2(xv.w, xv.w), w3.x, a01[j]);                \
            a23[j] = fma2_(pk2(xv.w, xv.w), w3.y, a23[j]);                \
        }                                                                 \
    }                                                                     \
    _Pragma("unroll")                                                     \
    for (int j = 0; j < 4; j++) {                                         \
        int node = blockIdx.x * NPB + lbase + 4 * j;                      \
        if (node < n_) {                                                  \
            ulonglong2 r; r.x = a01[j]; r.y = a23[j];                     \
            ((ulonglong2*)Y)[node * 8 + sub] = r;                        \
        }                                                                 \
    }

__global__ void __launch_bounds__(256)
gemm_fc1(const float4* __restrict__ x,
         const float* __restrict__ fc1w, const float* __restrict__ fc1b,
         const float* __restrict__ w, float4* __restrict__ Y, int n)
{
    __shared__ ulonglong2 swu[256];
    __shared__ float4 sx[NPB * 9];
    __shared__ float4 sfw[32];
    __shared__ float4 sfb[8];
    int tid = threadIdx.x;
    swu[tid] = ((const ulonglong2*)w)[tid];
    if (tid < 32) sfw[tid] = ((const float4*)fc1w)[tid];
    if (tid < 8)  sfb[tid] = ((const float4*)fc1b)[tid];
    __syncthreads();
    int ln = tid >> 1;
    int nd = blockIdx.x * NPB + ln;
    int half = (tid & 1) * 4;
    if (nd < n) {
        float4 xin = x[nd];
        #pragma unroll
        for (int i = 0; i < 4; i++) {
            int q = half + i;
            float4 h = sfb[q];
            float4 r0 = sfw[q], r1 = sfw[8 + q], r2 = sfw[16 + q], r3 = sfw[24 + q];
            h.x += xin.x * r0.x + xin.y * r1.x + xin.z * r2.x + xin.w * r3.x;
            h.y += xin.x * r0.y + xin.y * r1.y + xin.z * r2.y + xin.w * r3.y;
            h.z += xin.x * r0.z + xin.y * r1.z + xin.z * r2.z + xin.w * r3.z;
            h.w += xin.x * r0.w + xin.y * r1.w + xin.z * r2.w + xin.w * r3.w;
            sx[ln * 9 + q] = relu4(h);
        }
    }
    GEMM_COMPUTE(n)
}

__global__ void __launch_bounds__(256)
gemm_down(const float4* __restrict__ in, const float* __restrict__ w,
          float4* __restrict__ Y, int n, int hy, int win)
{
    __shared__ ulonglong2 swu[256];
    __shared__ float4 sx[NPB * 9];
    int tid = threadIdx.x;
    swu[tid] = ((const ulonglong2*)w)[tid];
    int ln = tid >> 1;
    int nd = blockIdx.x * NPB + ln;
    int half = (tid & 1) * 4;
    if (nd < n) {
        int ix = nd / hy, iy = nd - ix * hy;
        const float4* src = in + ((2 * ix) * win + 2 * iy) * 8 + half;
        #pragma unroll
        for (int i = 0; i < 4; i++)
            sx[ln * 9 + half + i] = relu4(src[i]);
    }
    GEMM_COMPUTE(n)
}

__global__ void __launch_bounds__(256)
gemm_upadd(const float4* __restrict__ base, const float4* __restrict__ coarse,
           const float* __restrict__ w, float4* __restrict__ Y, int n, int hy)
{
    __shared__ ulonglong2 swu[256];
    __shared__ float4 sx[NPB * 9];
    int tid = threadIdx.x;
    swu[tid] = ((const ulonglong2*)w)[tid];
    int ln = tid >> 1;
    int nd = blockIdx.x * NPB + ln;
    int half = (tid & 1) * 4;
    if (nd < n) {
        int ix = nd / hy, iy = nd - ix * hy;
        int cn = (ix >> 1) * (hy >> 1) + (iy >> 1);
        const float4* bsrc = base + nd * 8 + half;
        const float4* csrc = coarse + cn * 8 + half;
        #pragma unroll
        for (int i = 0; i < 4; i++) {
            float4 xb = relu4(bsrc[i]);
            float4 xc = relu4(csrc[i]);
            sx[ln * 9 + half + i] =
                make_float4(xb.x + xc.x, xb.y + xc.y, xb.z + xc.z, xb.w + xc.w);
        }
    }
    GEMM_COMPUTE(n)
}

// ---------------- gather (R9/R12 verbatim) ----------------
__device__ __forceinline__ void gather_acc(
    const ulonglong2* __restrict__ Y, int node, int sub, int gbase,
    const float* __restrict__ bias, ull& a01, ull& a23)
{
    float di = g_dinv[gbase + node];
    int beg = g_rowptr[gbase + node];
    int end = g_rowptr[gbase + node + 1];
    float4 bb = ((const float4*)bias)[sub];
    float s2 = di * di;
    ulonglong2 y = Y[node * 8 + sub];
    ull s22 = pk2(s2, s2);
    a01 = fma2_(y.x, s22, pk2(bb.x, bb.y));
    a23 = fma2_(y.y, s22, pk2(bb.z, bb.w));
    for (int p = beg; p < end; p++) {
        int s = g_eix[p];
        float nm = g_dinv[gbase + s] * di;
        ulonglong2 v = Y[s * 8 + sub];
        ull nn = pk2(nm, nm);
        a01 = fma2_(v.x, nn, a01);
        a23 = fma2_(v.y, nn, a23);
    }
}

__global__ void gather(const float4* __restrict__ Yf,
                       const float* __restrict__ bias,
                       float4* __restrict__ OUT, int n, int gbase)
{
    int t = blockIdx.x * blockDim.x + threadIdx.x;
    int node = t >> 3, sub = t & 7;
    if (node >= n) return;
    ull a01, a23;
    gather_acc((const ulonglong2*)Yf, node, sub, gbase, bias, a01, a23);
    ulonglong2 r; r.x = a01; r.y = a23;
    ((ulonglong2*)OUT)[node * 8 + sub] = r;
}

__global__ void gather_fc2(const float4* __restrict__ Yf,
                           const float* __restrict__ bias,
                           const float* __restrict__ w2, const float* __restrict__ b2,
                           float* __restrict__ out, int n)
{
    __shared__ float sw[96];
    int tid = threadIdx.x;
    if (tid < 96) sw[tid] = w2[tid];
    __syncthreads();
    int t = blockIdx.x * blockDim.x + tid;
    int node = t >> 3, sub = t & 7;
    if (node >= n) return;
    ull a01, a23;
    gather_acc((const ulonglong2*)Yf, node, sub, 0, bias, a01, a23);
    float2 v01 = up2_(a01), v23 = up2_(a23);
    float4 v = relu4(make_float4(v01.x, v01.y, v23.x, v23.y));
    int c = 4 * sub;
    float p0 = v.x * sw[(c+0)*3+0] + v.y * sw[(c+1)*3+0] + v.z * sw[(c+2)*3+0] + v.w * sw[(c+3)*3+0];
    float p1 = v.x * sw[(c+0)*3+1] + v.y * sw[(c+1)*3+1] + v.z * sw[(c+2)*3+1] + v.w * sw[(c+3)*3+1];
    float p2 = v.x * sw[(c+0)*3+2] + v.y * sw[(c+1)*3+2] + v.z * sw[(c+2)*3+2] + v.w * sw[(c+3)*3+2];
    #pragma unroll
    for (int off = 4; off; off >>= 1) {
        p0 += __shfl_down_sync(0xffffffffu, p0, off, 8);
        p1 += __shfl_down_sync(0xffffffffu, p1, off, 8);
        p2 += __shfl_down_sync(0xffffffffu, p2, off, 8);
    }
    if (sub == 0) {
        out[node * 3 + 0] = p0 + __ldg(&b2[0]);
        out[node * 3 + 1] = p1 + __ldg(&b2[1]);
        out[node * 3 + 2] = p2 + __ldg(&b2[2]);
    }
}

// ---------------------------------------------------------------------------
static inline int ceil_div(int a, int b) { return (a + b - 1) / b; }

static cudaStream_t g_s2 = 0;
static cudaEvent_t  g_evTop = 0, g_evZ = 0, g_evF = 0, g_ev12 = 0;

extern "C" void kernel_launch(void* const* d_in, const int* in_sizes, int n_in,
                              void* d_out, int out_size) {
    const float* x     = (const float*)d_in[0];
    const float* fc1_w = (const float*)d_in[1];
    const float* fc1_b = (const float*)d_in[2];
    const float* w1 = (const float*)d_in[3];  const float* b1 = (const float*)d_in[4];
    const float* w2 = (const float*)d_in[5];  const float* b2 = (const float*)d_in[6];
    const float* w3 = (const float*)d_in[7];  const float* b3 = (const float*)d_in[8];
    const float* w4 = (const float*)d_in[9];  const float* b4 = (const float*)d_in[10];
    const float* w5 = (const float*)d_in[11]; const float* b5 = (const float*)d_in[12];
    const float* fc2_w = (const float*)d_in[13];
    const float* fc2_b = (const float*)d_in[14];
    const int* ei0 = (const int*)d_in[18];
    const int* ei1 = (const int*)d_in[19];
    const int* ei2 = (const int*)d_in[20];
    float* out = (float*)d_out;

    float4 *Y, *H, *G2, *G4, *G3;
    int *bs0, *bs12;
    cudaGetSymbolAddress((void**)&Y,  g_Y);
    cudaGetSymbolAddress((void**)&H,  g_H);
    cudaGetSymbolAddress((void**)&G2, g_G2);
    cudaGetSymbolAddress((void**)&G4, g_G4);
    cudaGetSymbolAddress((void**)&G3, g_G3);
    cudaGetSymbolAddress((void**)&bs0, g_bsum0);
    cudaGetSymbolAddress((void**)&bs12, g_bsum12);

    if (!g_s2) {
        cudaStreamCreateWithFlags(&g_s2, cudaStreamNonBlocking);
        cudaEventCreateWithFlags(&g_evTop, cudaEventDisableTiming);
        cudaEventCreateWithFlags(&g_evZ, cudaEventDisableTiming);
        cudaEventCreateWithFlags(&g_evF, cudaEventDisableTiming);
        cudaEventCreateWithFlags(&g_ev12, cudaEventDisableTiming);
    }

    const int TB = 256;

    // Fork side stream from the capture stream.
    cudaEventRecord(g_evTop, 0);
    cudaStreamWaitEvent(g_s2, g_evTop, 0);

    // main: zero counters, then level-0 CSR build
    zero_cnt<<<ceil_div(M, TB), TB>>>();
    cudaEventRecord(g_evZ, 0);
    hist0<<<ceil_div(E0, TB), TB>>>(ei0 + E0);
    scanA_r<<<NBLK0, 256>>>(bs0, 0, N0);
    scanC2_r<<<NBLK0, 256>>>(bs0, 0, N0, 0, E0);
    fill0<<<ceil_div(E0, TB), TB>>>(ei0);

    // side: gemm_fc1 (independent), then level-1/2 CSR build (after zero)
    gemm_fc1<<<ceil_div(N0, NPB), TB, 0, g_s2>>>((const float4*)x, fc1_w, fc1_b,
                                                 w1, Y, N0);
    cudaEventRecord(g_evF, g_s2);
    cudaStreamWaitEvent(g_s2, g_evZ, 0);
    hist12<<<ceil_div(E12, TB), TB, 0, g_s2>>>(ei1 + E1, ei2 + E2);
    scanA_r<<<NBLK12, 256, 0, g_s2>>>(bs12, N0, M12);
    scanC2_r<<<NBLK12, 256, 0, g_s2>>>(bs12, N0, M12, E0, ETOT);
    fill12<<<ceil_div(E12, TB), TB, 0, g_s2>>>(ei1, ei2);
    cudaEventRecord(g_ev12, g_s2);

    // main: gather1 needs fill0 (main) + gemm_fc1 (side)
    cudaStreamWaitEvent(0, g_evF, 0);
    gather<<<N0 / 32, TB>>>(Y, b1, H, N0, 0);

    // join level-1/2 CSR before level-1 gather
    cudaStreamWaitEvent(0, g_ev12, 0);

    // GCN2
    gemm_down<<<ceil_div(N1, NPB), TB>>>(H, w2, Y, N1, NYg / 2, NYg);
    gather<<<N1 / 32, TB>>>(Y, b2, G2, N1, GB1);

    // GCN3
    gemm_down<<<ceil_div(N2, NPB), TB>>>(G2, w3, Y, N2, NYg / 4, NYg / 2);
    gather<<<N2 / 32, TB>>>(Y, b3, G3, N2, GB2);

    // GCN4
    gemm_upadd<<<ceil_div(N1, NPB), TB>>>(G2, G3, w4, Y, N1, NYg / 2);
    gather<<<N1 / 32, TB>>>(Y, b4, G4, N1, GB1);

    // GCN5 + fc2
    gemm_upadd<<<ceil_div(N0, NPB), TB>>>(H, G4, w5, Y, N0, NYg);
    gather_fc2<<<N0 / 32, TB>>>(Y, b5, fc2_w, fc2_b, out, N0);

    (void)in_sizes; (void)n_in; (void)out_size;
}